// round 1
// baseline (speedup 1.0000x reference)
#include <cuda_runtime.h>
#include <cuda_bf16.h>
#include <math.h>

#define BATCH 64
#define SEQ   512
#define ISZ   1024
#define HSZ   1024
#define N4    4096   // 4 * HSZ

// ------------------------- scratch (device globals) -------------------------
__device__ float  g_Wi[ISZ * N4];                 // [k][n], n = g*1024 + j   (16 MB)
__device__ float4 g_Whp[HSZ * HSZ];               // [k*1024 + j] -> (i,f,g,o) (16 MB)
__device__ float  g_bias[N4];
__device__ float4 g_xp[(size_t)SEQ * BATCH * HSZ];// [(t*64+b)*1024 + j] -> 4 gates (512 MB)
__device__ float  g_h[2][BATCH * HSZ];
__device__ float  g_c[BATCH * HSZ];

// ------------------------------ pack weights -------------------------------
__global__ void pack_kernel(
    const float* __restrict__ wii, const float* __restrict__ wif,
    const float* __restrict__ wig, const float* __restrict__ wio,
    const float* __restrict__ whi, const float* __restrict__ whf,
    const float* __restrict__ whg, const float* __restrict__ who,
    const float* __restrict__ bii, const float* __restrict__ bhi,
    const float* __restrict__ bif, const float* __restrict__ bhf,
    const float* __restrict__ big, const float* __restrict__ bhg,
    const float* __restrict__ bio, const float* __restrict__ bho)
{
    int idx = blockIdx.x * blockDim.x + threadIdx.x;
    if (idx < ISZ * HSZ) {
        int k = idx >> 10;
        int j = idx & 1023;
        g_Wi[k * N4 + j]        = wii[idx];
        g_Wi[k * N4 + 1024 + j] = wif[idx];
        g_Wi[k * N4 + 2048 + j] = wig[idx];
        g_Wi[k * N4 + 3072 + j] = wio[idx];
        g_Whp[idx] = make_float4(whi[idx], whf[idx], whg[idx], who[idx]);
    }
    if (idx < HSZ) {
        g_bias[idx]        = bii[idx] + bhi[idx];
        g_bias[1024 + idx] = bif[idx] + bhf[idx];
        g_bias[2048 + idx] = big[idx] + bhg[idx];
        g_bias[3072 + idx] = bio[idx] + bho[idx];
    }
}

// ------------------------------ init h/c -----------------------------------
__global__ void init_state_kernel()
{
    int i = blockIdx.x * blockDim.x + threadIdx.x;
    if (i < BATCH * HSZ) {
        g_h[0][i] = 0.0f;
        g_h[1][i] = 0.0f;
        g_c[i]    = 0.0f;
    }
}

// ------------------- x_proj = x @ Wi + bias  (tiled SGEMM) ------------------
// M = 32768 (b*512+t), N = 4096, K = 1024. Block tile 128x128x8, 256 threads,
// thread tile 8x8. Stores gate-interleaved into g_xp.
__global__ void __launch_bounds__(256) xproj_kernel(const float* __restrict__ x)
{
    __shared__ float As[8][128];
    __shared__ float Bs[8][128];

    const int bm = blockIdx.y;     // 0..255
    const int bn = blockIdx.x;     // 0..31
    const int tid = threadIdx.x;

    const int arow = tid >> 1;           // 0..127
    const int acol = (tid & 1) * 4;      // 0 or 4
    const int brow = tid >> 5;           // 0..7
    const int bcol = (tid & 31) * 4;     // 0..124

    const int tx = tid & 15;             // 0..15 -> N
    const int ty = tid >> 4;             // 0..15 -> M

    float acc[8][8];
#pragma unroll
    for (int i = 0; i < 8; i++)
#pragma unroll
        for (int j = 0; j < 8; j++) acc[i][j] = 0.0f;

    const float* Aptr = x + (size_t)(bm * 128) * ISZ;
    const float* Bptr = g_Wi + bn * 128;

    for (int k0 = 0; k0 < ISZ; k0 += 8) {
        float4 av = *(const float4*)(Aptr + (size_t)arow * ISZ + k0 + acol);
        As[acol + 0][arow] = av.x;
        As[acol + 1][arow] = av.y;
        As[acol + 2][arow] = av.z;
        As[acol + 3][arow] = av.w;
        float4 bv = *(const float4*)(Bptr + (size_t)(k0 + brow) * N4 + bcol);
        *(float4*)&Bs[brow][bcol] = bv;
        __syncthreads();

#pragma unroll
        for (int kk = 0; kk < 8; kk++) {
            float a[8], b[8];
#pragma unroll
            for (int i = 0; i < 8; i++) a[i] = As[kk][ty * 8 + i];
#pragma unroll
            for (int j = 0; j < 8; j++) b[j] = Bs[kk][tx * 8 + j];
#pragma unroll
            for (int i = 0; i < 8; i++)
#pragma unroll
                for (int j = 0; j < 8; j++) acc[i][j] += a[i] * b[j];
        }
        __syncthreads();
    }

    float* xpf = (float*)g_xp;
#pragma unroll
    for (int i = 0; i < 8; i++) {
        int m = bm * 128 + ty * 8 + i;
        int bidx = m >> 9;       // batch
        int t    = m & 511;      // timestep
        size_t rowbase = ((size_t)t * BATCH + bidx) * HSZ;
#pragma unroll
        for (int j = 0; j < 8; j++) {
            int n  = bn * 128 + tx * 8 + j;
            int g  = n >> 10;
            int jj = n & 1023;
            float v = acc[i][j] + g_bias[n];
            xpf[((rowbase + jj) << 2) + g] = v;
        }
    }
}

// --------------------------- one recurrence step ----------------------------
// gates[b][h][4] = sum_k h_in[b][k] * Whp[k][h][4]  (+ xp already has bias)
// Grid 256 blocks x 128 threads. Block: hc tile of 4, all 64 batches.
// Thread: tx = hc-in-tile (0..3), ty = batch pair (0..31); 8 accumulators.
__global__ void __launch_bounds__(128) lstm_step_kernel(int t)
{
    __shared__ float hs[128 * 66];   // transposed chunk: hs[k*66 + b], padded

    const float* __restrict__ h_in = g_h[t & 1];
    float* __restrict__ h_out      = g_h[(t + 1) & 1];

    const int tid = threadIdx.x;
    const int tx = tid & 3;          // 0..3
    const int ty = tid >> 2;         // 0..31
    const int hc = blockIdx.x * 4 + tx;   // 0..1023
    const int b0 = ty * 2;

    float a00 = 0.f, a01 = 0.f, a02 = 0.f, a03 = 0.f;
    float a10 = 0.f, a11 = 0.f, a12 = 0.f, a13 = 0.f;

    for (int k0 = 0; k0 < HSZ; k0 += 128) {
        // cooperative transpose-load of h chunk: 64 b x 128 k
#pragma unroll
        for (int i = 0; i < 16; i++) {
            int idx = i * 128 + tid;       // 0..2047 float4 groups
            int b   = idx >> 5;            // 0..63
            int kk  = (idx & 31) * 4;      // 0..124
            float4 v = *(const float4*)(h_in + b * HSZ + k0 + kk);
            hs[(kk + 0) * 66 + b] = v.x;
            hs[(kk + 1) * 66 + b] = v.y;
            hs[(kk + 2) * 66 + b] = v.z;
            hs[(kk + 3) * 66 + b] = v.w;
        }
        __syncthreads();

        const float4* Wp = g_Whp + (size_t)k0 * HSZ + hc;
#pragma unroll 8
        for (int k = 0; k < 128; k++) {
            float4 w  = Wp[(size_t)k * HSZ];
            float2 hv = *(const float2*)&hs[k * 66 + b0];
            a00 += hv.x * w.x; a01 += hv.x * w.y; a02 += hv.x * w.z; a03 += hv.x * w.w;
            a10 += hv.y * w.x; a11 += hv.y * w.y; a12 += hv.y * w.z; a13 += hv.y * w.w;
        }
        __syncthreads();
    }

    // fused LSTM cell epilogue for the two batches this thread owns
#pragma unroll
    for (int bb = 0; bb < 2; bb++) {
        int b = b0 + bb;
        float gi = bb ? a10 : a00;
        float gf = bb ? a11 : a01;
        float gg = bb ? a12 : a02;
        float go = bb ? a13 : a03;
        float4 xp = g_xp[((size_t)t * BATCH + b) * HSZ + hc];
        float ig = 1.0f / (1.0f + expf(-(gi + xp.x)));
        float fg = 1.0f / (1.0f + expf(-(gf + xp.y)));
        float cg = tanhf(gg + xp.z);
        float og = 1.0f / (1.0f + expf(-(go + xp.w)));
        int idx = b * HSZ + hc;
        float c = g_c[idx] * fg + ig * cg;
        g_c[idx] = c;
        h_out[idx] = og * tanhf(c);
    }
}

// ------------------------------- write output -------------------------------
__global__ void copy_out_kernel(float* __restrict__ out, int n)
{
    int i = blockIdx.x * blockDim.x + threadIdx.x;
    if (i >= n) return;
    if (i < BATCH * HSZ)            out[i] = g_h[0][i];            // h_T (SEQ even -> buf 0)
    else if (i < 2 * BATCH * HSZ)   out[i] = g_c[i - BATCH * HSZ]; // c_T
    else                            out[i] = 0.0f;
}

// --------------------------------- launcher ---------------------------------
extern "C" void kernel_launch(void* const* d_in, const int* in_sizes, int n_in,
                              void* d_out, int out_size)
{
    const float* x   = (const float*)d_in[0];
    const float* wii = (const float*)d_in[1];
    const float* bii = (const float*)d_in[2];
    const float* whi = (const float*)d_in[3];
    const float* bhi = (const float*)d_in[4];
    const float* wif = (const float*)d_in[5];
    const float* bif = (const float*)d_in[6];
    const float* whf = (const float*)d_in[7];
    const float* bhf = (const float*)d_in[8];
    const float* wig = (const float*)d_in[9];
    const float* big = (const float*)d_in[10];
    const float* whg = (const float*)d_in[11];
    const float* bhg = (const float*)d_in[12];
    const float* wio = (const float*)d_in[13];
    const float* bio = (const float*)d_in[14];
    const float* who = (const float*)d_in[15];
    const float* bho = (const float*)d_in[16];
    (void)in_sizes; (void)n_in;

    // 1. pack weights + biases
    pack_kernel<<<(ISZ * HSZ + 255) / 256, 256>>>(
        wii, wif, wig, wio, whi, whf, whg, who,
        bii, bhi, bif, bhf, big, bhg, bio, bho);

    // 2. zero h, c
    init_state_kernel<<<(BATCH * HSZ + 255) / 256, 256>>>();

    // 3. x_proj big GEMM (+bias), gate-interleaved layout
    xproj_kernel<<<dim3(N4 / 128, (BATCH * SEQ) / 128), 256>>>(x);

    // 4. 512 sequential recurrence steps
    for (int t = 0; t < SEQ; t++)
        lstm_step_kernel<<<HSZ / 4, 128>>>(t);

    // 5. emit (h_T, c_T)
    copy_out_kernel<<<(out_size + 255) / 256, 256>>>((float*)d_out, out_size);
}

// round 3
// speedup vs baseline: 3.0231x; 3.0231x over previous
#include <cuda_runtime.h>
#include <cuda_bf16.h>
#include <math.h>
#include <stdint.h>

#define BATCH 64
#define SEQ   512
#define HSZ   1024
#define N4    4096
#define MTOT  (BATCH * SEQ)   // 32768

// ============================ device scratch ================================
__device__ __align__(128) __nv_bfloat16 g_WiT_hi[(size_t)N4 * HSZ]; // [n'][k]
__device__ __align__(128) __nv_bfloat16 g_WiT_lo[(size_t)N4 * HSZ];
__device__ __align__(128) __nv_bfloat16 g_WhT_hi[(size_t)N4 * HSZ];
__device__ __align__(128) __nv_bfloat16 g_WhT_lo[(size_t)N4 * HSZ];
__device__ __align__(128) __nv_bfloat16 g_x_hi[(size_t)MTOT * HSZ]; // [b*512+t][k]
__device__ __align__(128) __nv_bfloat16 g_x_lo[(size_t)MTOT * HSZ];
__device__ __align__(128) float g_bias_p[N4];
__device__ __align__(128) float g_xp[(size_t)MTOT * N4];            // [t*64+b][n']
__device__ __align__(128) __nv_bfloat16 g_hhi[2][BATCH * HSZ];
__device__ __align__(128) __nv_bfloat16 g_hlo[2][BATCH * HSZ];
__device__ __align__(128) float g_hf[BATCH * HSZ];
__device__ __align__(128) float g_c[BATCH * HSZ];

// ============================ PTX helpers ===================================
__device__ __forceinline__ uint32_t smem_u32(const void* p) {
    uint32_t a;
    asm("{ .reg .u64 t; cvta.to.shared.u64 t, %1; cvt.u32.u64 %0, t; }" : "=r"(a) : "l"(p));
    return a;
}
__device__ __forceinline__ void ldm4(uint32_t addr, uint32_t r[4]) {
    asm volatile("ldmatrix.sync.aligned.m8n8.x4.shared.b16 {%0,%1,%2,%3}, [%4];"
                 : "=r"(r[0]), "=r"(r[1]), "=r"(r[2]), "=r"(r[3]) : "r"(addr));
}
__device__ __forceinline__ void hmma(float c[4], const uint32_t a[4], uint32_t b0, uint32_t b1) {
    asm volatile("mma.sync.aligned.m16n8k16.row.col.f32.bf16.bf16.f32 "
                 "{%0,%1,%2,%3},{%4,%5,%6,%7},{%8,%9},{%0,%1,%2,%3};"
                 : "+f"(c[0]), "+f"(c[1]), "+f"(c[2]), "+f"(c[3])
                 : "r"(a[0]), "r"(a[1]), "r"(a[2]), "r"(a[3]), "r"(b0), "r"(b1));
}
#define CP16(d, s)  asm volatile("cp.async.cg.shared.global [%0], [%1], 16;" ::"r"(d), "l"(s))
#define CPCOMMIT()  asm volatile("cp.async.commit_group;" ::: "memory")
#define CPWAIT1()   asm volatile("cp.async.wait_group 1;" ::: "memory")
#define CPWAIT0()   asm volatile("cp.async.wait_group 0;" ::: "memory")

#define SROW 144      // 64 bf16 = 128B data + 16B pad (conflict-free ldmatrix)

// ============================== pack weights ================================
// W?T_hi/lo[n'][k], n' = hc*4 + gate  (gate-interleaved, K contiguous)
__global__ void pack_w(const float* __restrict__ wii, const float* __restrict__ wif,
                       const float* __restrict__ wig, const float* __restrict__ wio,
                       const float* __restrict__ whi, const float* __restrict__ whf,
                       const float* __restrict__ whg, const float* __restrict__ who)
{
    __shared__ float tile[32][33];
    const float* srcs[8] = {wii, wif, wig, wio, whi, whf, whg, who};
    int z = blockIdx.z;
    const float* src = srcs[z];
    __nv_bfloat16* dh = (z < 4) ? g_WiT_hi : g_WhT_hi;
    __nv_bfloat16* dl = (z < 4) ? g_WiT_lo : g_WhT_lo;
    int g = z & 3;
    int k0 = blockIdx.x * 32, hc0 = blockIdx.y * 32;
    int tx = threadIdx.x, ty = threadIdx.y;   // (32, 8)
#pragma unroll
    for (int i = 0; i < 4; i++) {
        int k = k0 + ty + i * 8;
        tile[ty + i * 8][tx] = src[(size_t)k * HSZ + hc0 + tx];
    }
    __syncthreads();
#pragma unroll
    for (int i = 0; i < 4; i++) {
        int r = ty + i * 8;
        size_t np = (size_t)(hc0 + r) * 4 + g;
        float v = tile[tx][r];
        __nv_bfloat16 hi = __float2bfloat16(v);
        float lo = v - __bfloat162float(hi);
        dh[np * HSZ + k0 + tx] = hi;
        dl[np * HSZ + k0 + tx] = __float2bfloat16(lo);
    }
}

// ======================== init state + packed bias ==========================
__global__ void init_state(const float* __restrict__ bii, const float* __restrict__ bhi,
                           const float* __restrict__ bif, const float* __restrict__ bhf,
                           const float* __restrict__ big, const float* __restrict__ bhg,
                           const float* __restrict__ bio, const float* __restrict__ bho)
{
    int i = blockIdx.x * blockDim.x + threadIdx.x;
    if (i < BATCH * HSZ) {
        g_c[i] = 0.f; g_hf[i] = 0.f;
        __nv_bfloat16 z = __float2bfloat16(0.f);
        g_hhi[0][i] = z; g_hhi[1][i] = z;
        g_hlo[0][i] = z; g_hlo[1][i] = z;
    }
    if (i < N4) {
        int hc = i >> 2, g = i & 3;
        const float* bi[4] = {bii, bif, big, bio};
        const float* bh[4] = {bhi, bhf, bhg, bho};
        g_bias_p[i] = bi[g][hc] + bh[g][hc];
    }
}

// =========================== x -> bf16 hi/lo split ==========================
__global__ void conv_x(const float* __restrict__ x)
{
    size_t i = (size_t)blockIdx.x * blockDim.x + threadIdx.x;   // float4 index
    float4 v = ((const float4*)x)[i];
    __nv_bfloat16 h0 = __float2bfloat16(v.x);
    __nv_bfloat16 h1 = __float2bfloat16(v.y);
    __nv_bfloat16 h2 = __float2bfloat16(v.z);
    __nv_bfloat16 h3 = __float2bfloat16(v.w);
    __nv_bfloat16 l0 = __float2bfloat16(v.x - __bfloat162float(h0));
    __nv_bfloat16 l1 = __float2bfloat16(v.y - __bfloat162float(h1));
    __nv_bfloat16 l2 = __float2bfloat16(v.z - __bfloat162float(h2));
    __nv_bfloat16 l3 = __float2bfloat16(v.w - __bfloat162float(h3));
    ((__nv_bfloat162*)g_x_hi)[i * 2]     = __halves2bfloat162(h0, h1);
    ((__nv_bfloat162*)g_x_hi)[i * 2 + 1] = __halves2bfloat162(h2, h3);
    ((__nv_bfloat162*)g_x_lo)[i * 2]     = __halves2bfloat162(l0, l1);
    ((__nv_bfloat162*)g_x_lo)[i * 2 + 1] = __halves2bfloat162(l2, l3);
}

// ========================= xproj GEMM (HMMA) ================================
// D[m][n'] = x[m][:] . WiT[n'][:], M-tile 128, N-tile 128, K=1024 (chunks of 64)
// stage layout: AHI 0 (128*144) | ALO 18432 | BHI 36864 | BLO 55296 ; 3 stages
#define XSTG 73728
__global__ void __launch_bounds__(256, 1) xproj_mma()
{
    extern __shared__ __align__(128) char smem[];
    const uint32_t sb = smem_u32(smem);
    const int tid = threadIdx.x;
    const int n0 = blockIdx.x * 128, m0 = blockIdx.y * 128;
    const int wid = tid >> 5, l = tid & 31;
    const int wm = wid >> 1, wn = wid & 1;    // 4 x 2 warps

    auto load_chunk = [&](int c, int st) {
        uint32_t base = sb + (uint32_t)st * XSTG;
        int ko = c * 64;
#pragma unroll
        for (int j = 0; j < 4; j++) {
            int cid = tid * 4 + j;          // 0..1023
            int row = cid >> 3, kc = cid & 7;
            uint32_t doff = row * SROW + kc * 16;
            const __nv_bfloat16* a = g_x_hi + (size_t)(m0 + row) * HSZ + ko + kc * 8;
            CP16(base + doff,          a);
            CP16(base + 18432 + doff,  g_x_lo  + (size_t)(m0 + row) * HSZ + ko + kc * 8);
            CP16(base + 36864 + doff,  g_WiT_hi + (size_t)(n0 + row) * HSZ + ko + kc * 8);
            CP16(base + 55296 + doff,  g_WiT_lo + (size_t)(n0 + row) * HSZ + ko + kc * 8);
        }
        CPCOMMIT();
    };

    float acc[2][8][4];
#pragma unroll
    for (int i = 0; i < 2; i++)
#pragma unroll
        for (int j = 0; j < 8; j++)
#pragma unroll
            for (int k = 0; k < 4; k++) acc[i][j][k] = 0.f;

    const uint32_t aoff = (wm * 32 + (l & 15)) * SROW + (l >> 4) * 16;
    const uint32_t boff = 36864u + (wn * 64 + (l & 15)) * SROW + (l >> 4) * 16;

    load_chunk(0, 0);
    load_chunk(1, 1);

    for (int c = 0; c < 16; c++) {
        if (c < 15) { CPWAIT1(); } else { CPWAIT0(); }
        __syncthreads();
        if (c + 2 < 16) load_chunk(c + 2, (c + 2) % 3);
        uint32_t base = sb + (uint32_t)(c % 3) * XSTG;
#pragma unroll
        for (int ks = 0; ks < 4; ks++) {
            uint32_t aO = base + aoff + ks * 32;
            uint32_t bO = base + boff + ks * 32;
            uint32_t ah0[4], ah1[4], al0[4], al1[4];
            ldm4(aO,              ah0);
            ldm4(aO + 16 * SROW,  ah1);
            ldm4(aO + 18432,             al0);
            ldm4(aO + 18432 + 16 * SROW, al1);
#pragma unroll
            for (int nh = 0; nh < 4; nh++) {
                uint32_t bh[4], bl[4];
                ldm4(bO + nh * 16 * SROW,         bh);
                ldm4(bO + nh * 16 * SROW + 18432, bl);
                int nb = nh * 2;
                hmma(acc[0][nb],     ah0, bh[0], bh[2]);
                hmma(acc[0][nb + 1], ah0, bh[1], bh[3]);
                hmma(acc[1][nb],     ah1, bh[0], bh[2]);
                hmma(acc[1][nb + 1], ah1, bh[1], bh[3]);
                hmma(acc[0][nb],     ah0, bl[0], bl[2]);
                hmma(acc[0][nb + 1], ah0, bl[1], bl[3]);
                hmma(acc[1][nb],     ah1, bl[0], bl[2]);
                hmma(acc[1][nb + 1], ah1, bl[1], bl[3]);
                hmma(acc[0][nb],     al0, bh[0], bh[2]);
                hmma(acc[0][nb + 1], al0, bh[1], bh[3]);
                hmma(acc[1][nb],     al1, bh[0], bh[2]);
                hmma(acc[1][nb + 1], al1, bh[1], bh[3]);
            }
        }
    }

    // epilogue: bias + store to g_xp[(t*64+b)][n'],  m = b*512 + t
#pragma unroll
    for (int mi = 0; mi < 2; mi++) {
#pragma unroll
        for (int nb = 0; nb < 8; nb++) {
            int row = m0 + wm * 32 + mi * 16 + (l >> 2);
            int col = n0 + wn * 64 + nb * 8 + 2 * (l & 3);
            float2 bv = *(const float2*)&g_bias_p[col];
            size_t r0 = ((size_t)(row & 511) * BATCH + (row >> 9)) * N4;
            *(float2*)&g_xp[r0 + col] = make_float2(acc[mi][nb][0] + bv.x,
                                                    acc[mi][nb][1] + bv.y);
            int row2 = row + 8;
            size_t r1 = ((size_t)(row2 & 511) * BATCH + (row2 >> 9)) * N4;
            *(float2*)&g_xp[r1 + col] = make_float2(acc[mi][nb][2] + bv.x,
                                                    acc[mi][nb][3] + bv.y);
        }
    }
}

// ========================= recurrence step (HMMA) ===========================
// D[n'][b] = sum_k WhT[n'][k] * h[b][k]; 64 CTAs, M-tile 64, N = 64 batch.
// stage: WHI 0 (64*144) | WLO 9216 | HHI 18432 | HLO 27648 ; 3 stages (36864 each)
#define SSTG 36864
__global__ void __launch_bounds__(256, 1) step_mma(int t)
{
    extern __shared__ __align__(128) char smem[];
    const uint32_t sb = smem_u32(smem);
    const int tid = threadIdx.x;
    const int n0 = blockIdx.x * 64;
    const int wid = tid >> 5, l = tid & 31;
    const int wm = wid & 1, wn = wid >> 1;    // 2 x 4 warps
    const __nv_bfloat16* __restrict__ hhi = g_hhi[t & 1];
    const __nv_bfloat16* __restrict__ hlo = g_hlo[t & 1];

    auto load_chunk = [&](int c, int st) {
        uint32_t base = sb + (uint32_t)st * SSTG;
        int ko = c * 64;
#pragma unroll
        for (int j = 0; j < 2; j++) {
            int cid = tid * 2 + j;          // 0..511
            int row = cid >> 3, kc = cid & 7;
            uint32_t doff = row * SROW + kc * 16;
            CP16(base + doff,         g_WhT_hi + (size_t)(n0 + row) * HSZ + ko + kc * 8);
            CP16(base + 9216 + doff,  g_WhT_lo + (size_t)(n0 + row) * HSZ + ko + kc * 8);
            CP16(base + 18432 + doff, hhi + (size_t)row * HSZ + ko + kc * 8);
            CP16(base + 27648 + doff, hlo + (size_t)row * HSZ + ko + kc * 8);
        }
        CPCOMMIT();
    };

    float acc[2][2][4];
#pragma unroll
    for (int i = 0; i < 2; i++)
#pragma unroll
        for (int j = 0; j < 2; j++)
#pragma unroll
            for (int k = 0; k < 4; k++) acc[i][j][k] = 0.f;

    const uint32_t aoff = (wm * 32 + (l & 15)) * SROW + (l >> 4) * 16;
    const uint32_t boff = 18432u + (wn * 16 + (l & 15)) * SROW + (l >> 4) * 16;

    load_chunk(0, 0);
    load_chunk(1, 1);

    for (int c = 0; c < 16; c++) {
        if (c < 15) { CPWAIT1(); } else { CPWAIT0(); }
        __syncthreads();
        if (c + 2 < 16) load_chunk(c + 2, (c + 2) % 3);
        uint32_t base = sb + (uint32_t)(c % 3) * SSTG;
#pragma unroll
        for (int ks = 0; ks < 4; ks++) {
            uint32_t aO = base + aoff + ks * 32;
            uint32_t bO = base + boff + ks * 32;
            uint32_t ah0[4], ah1[4], al0[4], al1[4], bh[4], bl[4];
            ldm4(aO,             ah0);
            ldm4(aO + 16 * SROW, ah1);
            ldm4(aO + 9216,             al0);
            ldm4(aO + 9216 + 16 * SROW, al1);
            ldm4(bO,        bh);
            ldm4(bO + 9216, bl);
            hmma(acc[0][0], ah0, bh[0], bh[2]);
            hmma(acc[0][1], ah0, bh[1], bh[3]);
            hmma(acc[1][0], ah1, bh[0], bh[2]);
            hmma(acc[1][1], ah1, bh[1], bh[3]);
            hmma(acc[0][0], ah0, bl[0], bl[2]);
            hmma(acc[0][1], ah0, bl[1], bl[3]);
            hmma(acc[1][0], ah1, bl[0], bl[2]);
            hmma(acc[1][1], ah1, bl[1], bl[3]);
            hmma(acc[0][0], al0, bh[0], bh[2]);
            hmma(acc[0][1], al0, bh[1], bh[3]);
            hmma(acc[1][0], al1, bh[0], bh[2]);
            hmma(acc[1][1], al1, bh[1], bh[3]);
        }
    }
    __syncthreads();   // all warps done with smem stages -> safe to alias Ds

    // stage D [64 n'][64 b] to smem
    float* Ds = (float*)smem;   // stride 68 floats
#pragma unroll
    for (int mi = 0; mi < 2; mi++) {
#pragma unroll
        for (int nb = 0; nb < 2; nb++) {
            int row = wm * 32 + mi * 16 + (l >> 2);
            int col = wn * 16 + nb * 8 + 2 * (l & 3);
            Ds[row * 68 + col]           = acc[mi][nb][0];
            Ds[row * 68 + col + 1]       = acc[mi][nb][1];
            Ds[(row + 8) * 68 + col]     = acc[mi][nb][2];
            Ds[(row + 8) * 68 + col + 1] = acc[mi][nb][3];
        }
    }
    __syncthreads();

    // fused LSTM cell update: thread -> (b, 4 hc values)
    const int b = tid & 63, q = tid >> 6;
    const float* xprow = g_xp + ((size_t)t * BATCH + b) * N4 + n0;
    __nv_bfloat16* hhi_o = g_hhi[(t + 1) & 1];
    __nv_bfloat16* hlo_o = g_hlo[(t + 1) & 1];
#pragma unroll
    for (int j = 0; j < 4; j++) {
        int hcl = q * 4 + j;     // 0..15
        float iv = Ds[(hcl * 4 + 0) * 68 + b];
        float fv = Ds[(hcl * 4 + 1) * 68 + b];
        float gv = Ds[(hcl * 4 + 2) * 68 + b];
        float ov = Ds[(hcl * 4 + 3) * 68 + b];
        float4 xp = *(const float4*)(xprow + hcl * 4);
        float ig = 1.0f / (1.0f + expf(-(iv + xp.x)));
        float fg = 1.0f / (1.0f + expf(-(fv + xp.y)));
        float gg = tanhf(gv + xp.z);
        float og = 1.0f / (1.0f + expf(-(ov + xp.w)));
        int idx = b * HSZ + blockIdx.x * 16 + hcl;
        float cnew = g_c[idx] * fg + ig * gg;
        g_c[idx] = cnew;
        float h = og * tanhf(cnew);
        g_hf[idx] = h;
        __nv_bfloat16 hh = __float2bfloat16(h);
        float lo = h - __bfloat162float(hh);
        hhi_o[idx] = hh;
        hlo_o[idx] = __float2bfloat16(lo);
    }
}

// ============================== output ======================================
__global__ void copy_out_kernel(float* __restrict__ out, int n)
{
    int i = blockIdx.x * blockDim.x + threadIdx.x;
    if (i >= n) return;
    if (i < BATCH * HSZ)          out[i] = g_hf[i];
    else if (i < 2 * BATCH * HSZ) out[i] = g_c[i - BATCH * HSZ];
    else                          out[i] = 0.0f;
}

// ============================== launcher ====================================
extern "C" void kernel_launch(void* const* d_in, const int* in_sizes, int n_in,
                              void* d_out, int out_size)
{
    const float* x   = (const float*)d_in[0];
    const float* wii = (const float*)d_in[1];
    const float* bii = (const float*)d_in[2];
    const float* whi = (const float*)d_in[3];
    const float* bhi = (const float*)d_in[4];
    const float* wif = (const float*)d_in[5];
    const float* bif = (const float*)d_in[6];
    const float* whf = (const float*)d_in[7];
    const float* bhf = (const float*)d_in[8];
    const float* wig = (const float*)d_in[9];
    const float* big = (const float*)d_in[10];
    const float* whg = (const float*)d_in[11];
    const float* bhg = (const float*)d_in[12];
    const float* wio = (const float*)d_in[13];
    const float* bio = (const float*)d_in[14];
    const float* who = (const float*)d_in[15];
    const float* bho = (const float*)d_in[16];
    (void)in_sizes; (void)n_in;

    static int configured = 0;
    if (!configured) {
        cudaFuncSetAttribute(xproj_mma, cudaFuncAttributeMaxDynamicSharedMemorySize, 3 * XSTG);
        cudaFuncSetAttribute(step_mma,  cudaFuncAttributeMaxDynamicSharedMemorySize, 3 * SSTG);
        configured = 1;
    }

    pack_w<<<dim3(32, 32, 8), dim3(32, 8)>>>(wii, wif, wig, wio, whi, whf, whg, who);
    init_state<<<(BATCH * HSZ + 255) / 256, 256>>>(bii, bhi, bif, bhf, big, bhg, bio, bho);
    conv_x<<<(MTOT * HSZ / 4 + 255) / 256, 256>>>(x);

    xproj_mma<<<dim3(32, 256), 256, 3 * XSTG>>>();

    for (int t = 0; t < SEQ; t++)
        step_mma<<<64, 256, 3 * SSTG>>>(t);

    copy_out_kernel<<<(out_size + 255) / 256, 256>>>((float*)d_out, out_size);
}

// round 4
// speedup vs baseline: 4.7794x; 1.5810x over previous
#include <cuda_runtime.h>
#include <cuda_bf16.h>
#include <math.h>
#include <stdint.h>

#define BATCH 64
#define SEQ   512
#define HSZ   1024
#define N4    4096
#define MTOT  (BATCH * SEQ)   // 32768
#define NCTA  128

// ============================ device scratch ================================
__device__ __align__(128) __nv_bfloat16 g_WiT_hi[(size_t)N4 * HSZ]; // [n'][k]
__device__ __align__(128) __nv_bfloat16 g_WiT_lo[(size_t)N4 * HSZ];
__device__ __align__(128) __nv_bfloat16 g_WhT_hi[(size_t)N4 * HSZ];
__device__ __align__(128) __nv_bfloat16 g_WhT_lo[(size_t)N4 * HSZ];
__device__ __align__(128) __nv_bfloat16 g_x_hi[(size_t)MTOT * HSZ]; // [b*512+t][k]
__device__ __align__(128) __nv_bfloat16 g_x_lo[(size_t)MTOT * HSZ];
__device__ __align__(128) float g_bias_p[N4];
__device__ __align__(128) float g_xp[(size_t)MTOT * N4];            // [t*64+b][n']
__device__ __align__(128) __nv_bfloat16 g_hhi[2][BATCH * HSZ];
__device__ __align__(128) __nv_bfloat16 g_hlo[2][BATCH * HSZ];
__device__ __align__(128) float g_hf[BATCH * HSZ];
__device__ __align__(128) float g_c[BATCH * HSZ];
__device__ unsigned g_bcnt;
__device__ unsigned g_bflag;

// ============================ PTX helpers ===================================
__device__ __forceinline__ uint32_t smem_u32(const void* p) {
    uint32_t a;
    asm("{ .reg .u64 t; cvta.to.shared.u64 t, %1; cvt.u32.u64 %0, t; }" : "=r"(a) : "l"(p));
    return a;
}
__device__ __forceinline__ void ldm4(uint32_t addr, uint32_t r[4]) {
    asm volatile("ldmatrix.sync.aligned.m8n8.x4.shared.b16 {%0,%1,%2,%3}, [%4];"
                 : "=r"(r[0]), "=r"(r[1]), "=r"(r[2]), "=r"(r[3]) : "r"(addr));
}
__device__ __forceinline__ void hmma(float c[4], const uint32_t a[4], uint32_t b0, uint32_t b1) {
    asm volatile("mma.sync.aligned.m16n8k16.row.col.f32.bf16.bf16.f32 "
                 "{%0,%1,%2,%3},{%4,%5,%6,%7},{%8,%9},{%0,%1,%2,%3};"
                 : "+f"(c[0]), "+f"(c[1]), "+f"(c[2]), "+f"(c[3])
                 : "r"(a[0]), "r"(a[1]), "r"(a[2]), "r"(a[3]), "r"(b0), "r"(b1));
}
#define CP16(d, s)  asm volatile("cp.async.cg.shared.global [%0], [%1], 16;" ::"r"(d), "l"(s))
#define CPCOMMIT()  asm volatile("cp.async.commit_group;" ::: "memory")
#define CPWAIT1()   asm volatile("cp.async.wait_group 1;" ::: "memory")
#define CPWAIT0()   asm volatile("cp.async.wait_group 0;" ::: "memory")

#define SROW 144      // 64 bf16 = 128B data + 16B pad (conflict-free ldmatrix)

// =========================== grid barrier ===================================
__device__ __forceinline__ void grid_barrier(unsigned target) {
    __threadfence();
    __syncthreads();
    if (threadIdx.x == 0) {
        unsigned total = (unsigned)NCTA * target;
        unsigned old = atomicAdd(&g_bcnt, 1u);
        if (old == total - 1u) {
            asm volatile("st.global.release.gpu.u32 [%0], %1;" ::"l"(&g_bflag), "r"(target) : "memory");
        } else {
            unsigned f;
            do {
                asm volatile("ld.global.acquire.gpu.u32 %0, [%1];" : "=r"(f) : "l"(&g_bflag) : "memory");
            } while (f < target);
        }
    }
    __syncthreads();
}

// ============================== pack weights ================================
// W?T_hi/lo[n'][k], n' = hc*4 + gate  (gate-interleaved, K contiguous)
__global__ void pack_w(const float* __restrict__ wii, const float* __restrict__ wif,
                       const float* __restrict__ wig, const float* __restrict__ wio,
                       const float* __restrict__ whi, const float* __restrict__ whf,
                       const float* __restrict__ whg, const float* __restrict__ who)
{
    __shared__ float tile[32][33];
    const float* srcs[8] = {wii, wif, wig, wio, whi, whf, whg, who};
    int z = blockIdx.z;
    const float* src = srcs[z];
    __nv_bfloat16* dh = (z < 4) ? g_WiT_hi : g_WhT_hi;
    __nv_bfloat16* dl = (z < 4) ? g_WiT_lo : g_WhT_lo;
    int g = z & 3;
    int k0 = blockIdx.x * 32, hc0 = blockIdx.y * 32;
    int tx = threadIdx.x, ty = threadIdx.y;   // (32, 8)
#pragma unroll
    for (int i = 0; i < 4; i++) {
        int k = k0 + ty + i * 8;
        tile[ty + i * 8][tx] = src[(size_t)k * HSZ + hc0 + tx];
    }
    __syncthreads();
#pragma unroll
    for (int i = 0; i < 4; i++) {
        int r = ty + i * 8;
        size_t np = (size_t)(hc0 + r) * 4 + g;
        float v = tile[tx][r];
        __nv_bfloat16 hi = __float2bfloat16(v);
        float lo = v - __bfloat162float(hi);
        dh[np * HSZ + k0 + tx] = hi;
        dl[np * HSZ + k0 + tx] = __float2bfloat16(lo);
    }
}

// ======================== init state + packed bias ==========================
__global__ void init_state(const float* __restrict__ bii, const float* __restrict__ bhi,
                           const float* __restrict__ bif, const float* __restrict__ bhf,
                           const float* __restrict__ big, const float* __restrict__ bhg,
                           const float* __restrict__ bio, const float* __restrict__ bho)
{
    int i = blockIdx.x * blockDim.x + threadIdx.x;
    if (i == 0) { g_bcnt = 0u; g_bflag = 0u; }
    if (i < BATCH * HSZ) {
        __nv_bfloat16 z = __float2bfloat16(0.f);
        g_hhi[0][i] = z; g_hhi[1][i] = z;
        g_hlo[0][i] = z; g_hlo[1][i] = z;
    }
    if (i < N4) {
        int hc = i >> 2, g = i & 3;
        const float* bi[4] = {bii, bif, big, bio};
        const float* bh[4] = {bhi, bhf, bhg, bho};
        g_bias_p[i] = bi[g][hc] + bh[g][hc];
    }
}

// =========================== x -> bf16 hi/lo split ==========================
__global__ void conv_x(const float* __restrict__ x)
{
    size_t i = (size_t)blockIdx.x * blockDim.x + threadIdx.x;   // float4 index
    float4 v = ((const float4*)x)[i];
    __nv_bfloat16 h0 = __float2bfloat16(v.x);
    __nv_bfloat16 h1 = __float2bfloat16(v.y);
    __nv_bfloat16 h2 = __float2bfloat16(v.z);
    __nv_bfloat16 h3 = __float2bfloat16(v.w);
    __nv_bfloat16 l0 = __float2bfloat16(v.x - __bfloat162float(h0));
    __nv_bfloat16 l1 = __float2bfloat16(v.y - __bfloat162float(h1));
    __nv_bfloat16 l2 = __float2bfloat16(v.z - __bfloat162float(h2));
    __nv_bfloat16 l3 = __float2bfloat16(v.w - __bfloat162float(h3));
    ((__nv_bfloat162*)g_x_hi)[i * 2]     = __halves2bfloat162(h0, h1);
    ((__nv_bfloat162*)g_x_hi)[i * 2 + 1] = __halves2bfloat162(h2, h3);
    ((__nv_bfloat162*)g_x_lo)[i * 2]     = __halves2bfloat162(l0, l1);
    ((__nv_bfloat162*)g_x_lo)[i * 2 + 1] = __halves2bfloat162(l2, l3);
}

// ========================= xproj GEMM (HMMA) ================================
// D[m][n'] = x[m][:] . WiT[n'][:], M-tile 128, N-tile 128, K=1024 (chunks of 64)
#define XSTG 73728
__global__ void __launch_bounds__(256, 1) xproj_mma()
{
    extern __shared__ __align__(128) char smem[];
    const uint32_t sb = smem_u32(smem);
    const int tid = threadIdx.x;
    const int n0 = blockIdx.x * 128, m0 = blockIdx.y * 128;
    const int wid = tid >> 5, l = tid & 31;
    const int wm = wid >> 1, wn = wid & 1;    // 4 x 2 warps

    auto load_chunk = [&](int c, int st) {
        uint32_t base = sb + (uint32_t)st * XSTG;
        int ko = c * 64;
#pragma unroll
        for (int j = 0; j < 4; j++) {
            int cid = tid * 4 + j;          // 0..1023
            int row = cid >> 3, kc = cid & 7;
            uint32_t doff = row * SROW + kc * 16;
            CP16(base + doff,          g_x_hi  + (size_t)(m0 + row) * HSZ + ko + kc * 8);
            CP16(base + 18432 + doff,  g_x_lo  + (size_t)(m0 + row) * HSZ + ko + kc * 8);
            CP16(base + 36864 + doff,  g_WiT_hi + (size_t)(n0 + row) * HSZ + ko + kc * 8);
            CP16(base + 55296 + doff,  g_WiT_lo + (size_t)(n0 + row) * HSZ + ko + kc * 8);
        }
        CPCOMMIT();
    };

    float acc[2][8][4];
#pragma unroll
    for (int i = 0; i < 2; i++)
#pragma unroll
        for (int j = 0; j < 8; j++)
#pragma unroll
            for (int k = 0; k < 4; k++) acc[i][j][k] = 0.f;

    const uint32_t aoff = (wm * 32 + (l & 15)) * SROW + (l >> 4) * 16;
    const uint32_t boff = 36864u + (wn * 64 + (l & 15)) * SROW + (l >> 4) * 16;

    load_chunk(0, 0);
    load_chunk(1, 1);

    for (int c = 0; c < 16; c++) {
        if (c < 15) { CPWAIT1(); } else { CPWAIT0(); }
        __syncthreads();
        if (c + 2 < 16) load_chunk(c + 2, (c + 2) % 3);
        uint32_t base = sb + (uint32_t)(c % 3) * XSTG;
#pragma unroll
        for (int ks = 0; ks < 4; ks++) {
            uint32_t aO = base + aoff + ks * 32;
            uint32_t bO = base + boff + ks * 32;
            uint32_t ah0[4], ah1[4], al0[4], al1[4];
            ldm4(aO,              ah0);
            ldm4(aO + 16 * SROW,  ah1);
            ldm4(aO + 18432,             al0);
            ldm4(aO + 18432 + 16 * SROW, al1);
#pragma unroll
            for (int nh = 0; nh < 4; nh++) {
                uint32_t bh[4], bl[4];
                ldm4(bO + nh * 16 * SROW,         bh);
                ldm4(bO + nh * 16 * SROW + 18432, bl);
                int nb = nh * 2;
                hmma(acc[0][nb],     ah0, bh[0], bh[2]);
                hmma(acc[0][nb + 1], ah0, bh[1], bh[3]);
                hmma(acc[1][nb],     ah1, bh[0], bh[2]);
                hmma(acc[1][nb + 1], ah1, bh[1], bh[3]);
                hmma(acc[0][nb],     ah0, bl[0], bl[2]);
                hmma(acc[0][nb + 1], ah0, bl[1], bl[3]);
                hmma(acc[1][nb],     ah1, bl[0], bl[2]);
                hmma(acc[1][nb + 1], ah1, bl[1], bl[3]);
                hmma(acc[0][nb],     al0, bh[0], bh[2]);
                hmma(acc[0][nb + 1], al0, bh[1], bh[3]);
                hmma(acc[1][nb],     al1, bh[0], bh[2]);
                hmma(acc[1][nb + 1], al1, bh[1], bh[3]);
            }
        }
    }

    // epilogue: bias + store to g_xp[(t*64+b)][n'],  m = b*512 + t
#pragma unroll
    for (int mi = 0; mi < 2; mi++) {
#pragma unroll
        for (int nb = 0; nb < 8; nb++) {
            int row = m0 + wm * 32 + mi * 16 + (l >> 2);
            int col = n0 + wn * 64 + nb * 8 + 2 * (l & 3);
            float2 bv = *(const float2*)&g_bias_p[col];
            size_t r0 = ((size_t)(row & 511) * BATCH + (row >> 9)) * N4;
            *(float2*)&g_xp[r0 + col] = make_float2(acc[mi][nb][0] + bv.x,
                                                    acc[mi][nb][1] + bv.y);
            int row2 = row + 8;
            size_t r1 = ((size_t)(row2 & 511) * BATCH + (row2 >> 9)) * N4;
            *(float2*)&g_xp[r1 + col] = make_float2(acc[mi][nb][2] + bv.x,
                                                    acc[mi][nb][3] + bv.y);
        }
    }
}

// ==================== persistent recurrence (all 512 steps) =================
// 128 CTAs x 256 thr. CTA owns n' rows [cta*32, cta*32+32) (= 8 h-cells x 4 gates),
// W slice resident in smem (hi+lo). Per step: stream h (hi/lo) via cp.async,
// 3-term HMMA, fused cell update, grid barrier.
#define WROWS   32
#define WSTRIDE 2064                       // 2048B data + 16B pad
#define WOFF_LO (WROWS * WSTRIDE)          // 66048
#define HOFF    (2 * WROWS * WSTRIDE)      // 132096
#define HSTG    18432                      // stage: hi 9216 + lo 9216
#define DSOFF   (HOFF + 3 * HSTG)          // 187392
#define PCOFF   (DSOFF + 32 * 68 * 4)      // 196096
#define PSMEM   (PCOFF + 512 * 4)          // 198144

__global__ void __launch_bounds__(256, 1) lstm_persist()
{
    extern __shared__ __align__(128) char smem[];
    const uint32_t sb = smem_u32(smem);
    const int tid = threadIdx.x;
    const int cta = blockIdx.x;
    const int n0 = cta * WROWS;
    const int wid = tid >> 5, l = tid & 31;
    const int wm = wid & 1, wn = wid >> 1;    // 2 m-halves x 4 n-quarters

    // ---- load resident W slice (hi & lo), 132 KB ----
    for (int i = tid; i < 4096; i += 256) {
        int row = i >> 7, c16 = i & 127;
        uint32_t d = sb + row * WSTRIDE + c16 * 16;
        CP16(d,           g_WhT_hi + (size_t)(n0 + row) * HSZ + c16 * 8);
        CP16(d + WOFF_LO, g_WhT_lo + (size_t)(n0 + row) * HSZ + c16 * 8);
    }
    CPCOMMIT(); CPWAIT0();

    float* c_s = (float*)(smem + PCOFF);
    float* Ds  = (float*)(smem + DSOFF);
    for (int i = tid; i < 512; i += 256) c_s[i] = 0.f;
    __syncthreads();

    const uint32_t aoffh = sb + (wm * 16 + (l & 15)) * WSTRIDE + (l >> 4) * 16;
    const uint32_t aoffl = aoffh + WOFF_LO;
    const uint32_t boffr = (wn * 16 + (l & 15)) * SROW + (l >> 4) * 16;

    const int b = tid & 63, q = tid >> 6;     // cell ownership: (b, hc=2q..2q+1)
    const int hcg0 = cta * 8 + 2 * q;         // global h-cell base for this thread

    for (int t = 0; t < SEQ; t++) {
        const __nv_bfloat16* __restrict__ hhi = g_hhi[t & 1];
        const __nv_bfloat16* __restrict__ hlo = g_hlo[t & 1];

        // prefetch xp tile (independent of h) into registers
        const float* xprow = g_xp + ((size_t)t * BATCH + b) * N4 + n0 + q * 8;
        float4 xpA = *(const float4*)(xprow);
        float4 xpB = *(const float4*)(xprow + 4);

        auto load_h = [&](int c, int st) {
            uint32_t base = sb + HOFF + (uint32_t)st * HSTG;
            int ko = c * 64;
#pragma unroll
            for (int j = 0; j < 2; j++) {
                int cid = tid * 2 + j;        // 0..511
                int row = cid >> 3, kc = cid & 7;
                uint32_t doff = row * SROW + kc * 16;
                CP16(base + doff,        hhi + (size_t)row * HSZ + ko + kc * 8);
                CP16(base + 9216 + doff, hlo + (size_t)row * HSZ + ko + kc * 8);
            }
            CPCOMMIT();
        };

        float acc[2][4];
#pragma unroll
        for (int i = 0; i < 2; i++)
#pragma unroll
            for (int k = 0; k < 4; k++) acc[i][k] = 0.f;

        load_h(0, 0);
        load_h(1, 1);

        for (int c = 0; c < 16; c++) {
            if (c < 15) { CPWAIT1(); } else { CPWAIT0(); }
            __syncthreads();
            if (c + 2 < 16) load_h(c + 2, (c + 2) % 3);
            uint32_t hb = sb + HOFF + (uint32_t)(c % 3) * HSTG;
#pragma unroll
            for (int ks = 0; ks < 4; ks++) {
                uint32_t aO = aoffh + c * 128 + ks * 32;
                uint32_t lO = aoffl + c * 128 + ks * 32;
                uint32_t bO = hb + boffr + ks * 32;
                uint32_t ah[4], al[4], bh[4], bl[4];
                ldm4(aO, ah);
                ldm4(lO, al);
                ldm4(bO, bh);
                ldm4(bO + 9216, bl);
                hmma(acc[0], ah, bh[0], bh[2]);
                hmma(acc[1], ah, bh[1], bh[3]);
                hmma(acc[0], ah, bl[0], bl[2]);
                hmma(acc[1], ah, bl[1], bl[3]);
                hmma(acc[0], al, bh[0], bh[2]);
                hmma(acc[1], al, bh[1], bh[3]);
            }
            __syncthreads();   // stage consumed; next prefetch may overwrite
        }

        // D [32 n'][64 b] -> smem
        {
            int r = wm * 16 + (l >> 2);
#pragma unroll
            for (int nb = 0; nb < 2; nb++) {
                int col = wn * 16 + nb * 8 + 2 * (l & 3);
                Ds[r * 68 + col]           = acc[nb][0];
                Ds[r * 68 + col + 1]       = acc[nb][1];
                Ds[(r + 8) * 68 + col]     = acc[nb][2];
                Ds[(r + 8) * 68 + col + 1] = acc[nb][3];
            }
        }
        __syncthreads();

        // fused cell update: this thread owns (b, hc=2q) and (b, hc=2q+1)
        float hv[2];
#pragma unroll
        for (int j = 0; j < 2; j++) {
            int hcl = 2 * q + j;
            float iv = Ds[(hcl * 4 + 0) * 68 + b];
            float fv = Ds[(hcl * 4 + 1) * 68 + b];
            float gv = Ds[(hcl * 4 + 2) * 68 + b];
            float ov = Ds[(hcl * 4 + 3) * 68 + b];
            float xi = j ? xpB.x : xpA.x;
            float xf = j ? xpB.y : xpA.y;
            float xg = j ? xpB.z : xpA.z;
            float xo = j ? xpB.w : xpA.w;
            float ig = 1.0f / (1.0f + expf(-(iv + xi)));
            float fg = 1.0f / (1.0f + expf(-(fv + xf)));
            float gg = tanhf(gv + xg);
            float og = 1.0f / (1.0f + expf(-(ov + xo)));
            int ci = b * 8 + hcl;
            float cnew = c_s[ci] * fg + ig * gg;
            c_s[ci] = cnew;
            hv[j] = og * tanhf(cnew);
        }
        // write h_{t+1} (bf16 hi/lo pairs, 4B each)
        {
            __nv_bfloat16 h0 = __float2bfloat16(hv[0]);
            __nv_bfloat16 h1 = __float2bfloat16(hv[1]);
            __nv_bfloat16 l0 = __float2bfloat16(hv[0] - __bfloat162float(h0));
            __nv_bfloat16 l1 = __float2bfloat16(hv[1] - __bfloat162float(h1));
            int idx = b * HSZ + hcg0;
            *(__nv_bfloat162*)(g_hhi[(t + 1) & 1] + idx) = __halves2bfloat162(h0, h1);
            *(__nv_bfloat162*)(g_hlo[(t + 1) & 1] + idx) = __halves2bfloat162(l0, l1);
            if (t == SEQ - 1) {
                *(float2*)(g_hf + idx) = make_float2(hv[0], hv[1]);
                *(float2*)(g_c  + idx) = make_float2(c_s[b * 8 + 2 * q], c_s[b * 8 + 2 * q + 1]);
            }
        }
        __syncthreads();           // Ds/c_s stable before next step reuses them

        if (t < SEQ - 1) grid_barrier((unsigned)(t + 1));
    }
}

// ============================== output ======================================
__global__ void copy_out_kernel(float* __restrict__ out, int n)
{
    int i = blockIdx.x * blockDim.x + threadIdx.x;
    if (i >= n) return;
    if (i < BATCH * HSZ)          out[i] = g_hf[i];
    else if (i < 2 * BATCH * HSZ) out[i] = g_c[i - BATCH * HSZ];
    else                          out[i] = 0.0f;
}

// ============================== launcher ====================================
extern "C" void kernel_launch(void* const* d_in, const int* in_sizes, int n_in,
                              void* d_out, int out_size)
{
    const float* x   = (const float*)d_in[0];
    const float* wii = (const float*)d_in[1];
    const float* bii = (const float*)d_in[2];
    const float* whi = (const float*)d_in[3];
    const float* bhi = (const float*)d_in[4];
    const float* wif = (const float*)d_in[5];
    const float* bif = (const float*)d_in[6];
    const float* whf = (const float*)d_in[7];
    const float* bhf = (const float*)d_in[8];
    const float* wig = (const float*)d_in[9];
    const float* big = (const float*)d_in[10];
    const float* whg = (const float*)d_in[11];
    const float* bhg = (const float*)d_in[12];
    const float* wio = (const float*)d_in[13];
    const float* bio = (const float*)d_in[14];
    const float* who = (const float*)d_in[15];
    const float* bho = (const float*)d_in[16];
    (void)in_sizes; (void)n_in;

    static int configured = 0;
    if (!configured) {
        cudaFuncSetAttribute(xproj_mma,    cudaFuncAttributeMaxDynamicSharedMemorySize, 3 * XSTG);
        cudaFuncSetAttribute(lstm_persist, cudaFuncAttributeMaxDynamicSharedMemorySize, PSMEM);
        configured = 1;
    }

    pack_w<<<dim3(32, 32, 8), dim3(32, 8)>>>(wii, wif, wig, wio, whi, whf, whg, who);
    init_state<<<(BATCH * HSZ + 255) / 256, 256>>>(bii, bhi, bif, bhf, big, bhg, bio, bho);
    conv_x<<<(MTOT * HSZ / 4 + 255) / 256, 256>>>(x);

    xproj_mma<<<dim3(32, 256), 256, 3 * XSTG>>>();

    lstm_persist<<<NCTA, 256, PSMEM>>>();

    copy_out_kernel<<<(out_size + 255) / 256, 256>>>((float*)d_out, out_size);
}

// round 5
// speedup vs baseline: 4.9709x; 1.0401x over previous
#include <cuda_runtime.h>
#include <cuda_bf16.h>
#include <cuda_fp16.h>
#include <math.h>
#include <stdint.h>

#define BATCH 64
#define SEQ   512
#define HSZ   1024
#define N4    4096
#define MTOT  (BATCH * SEQ)   // 32768
#define NCTA  128

// ============================ device scratch ================================
__device__ __align__(128) __nv_bfloat16 g_WiT_hi[(size_t)N4 * HSZ]; // [n'][k]
__device__ __align__(128) __nv_bfloat16 g_WiT_lo[(size_t)N4 * HSZ];
__device__ __align__(128) __half g_WhT_h[(size_t)N4 * HSZ];         // fp16 hi
__device__ __align__(128) __half g_WhT_l[(size_t)N4 * HSZ];         // fp16 (lo*2048)
__device__ __align__(128) __nv_bfloat16 g_x_hi[(size_t)MTOT * HSZ]; // [b*512+t][k]
__device__ __align__(128) __nv_bfloat16 g_x_lo[(size_t)MTOT * HSZ];
__device__ __align__(128) float g_bias_p[N4];
__device__ __align__(128) float g_xp[(size_t)MTOT * N4];            // [t*64+b][n']
__device__ __align__(128) __half g_h16[2][BATCH * HSZ];
__device__ __align__(128) float g_hf[BATCH * HSZ];
__device__ __align__(128) float g_c[BATCH * HSZ];
__device__ unsigned g_bcnt;
__device__ unsigned g_bflag;

// ============================ PTX helpers ===================================
__device__ __forceinline__ uint32_t smem_u32(const void* p) {
    uint32_t a;
    asm("{ .reg .u64 t; cvta.to.shared.u64 t, %1; cvt.u32.u64 %0, t; }" : "=r"(a) : "l"(p));
    return a;
}
__device__ __forceinline__ void ldm4(uint32_t addr, uint32_t r[4]) {
    asm volatile("ldmatrix.sync.aligned.m8n8.x4.shared.b16 {%0,%1,%2,%3}, [%4];"
                 : "=r"(r[0]), "=r"(r[1]), "=r"(r[2]), "=r"(r[3]) : "r"(addr));
}
__device__ __forceinline__ void hmma_bf16(float c[4], const uint32_t a[4], uint32_t b0, uint32_t b1) {
    asm volatile("mma.sync.aligned.m16n8k16.row.col.f32.bf16.bf16.f32 "
                 "{%0,%1,%2,%3},{%4,%5,%6,%7},{%8,%9},{%0,%1,%2,%3};"
                 : "+f"(c[0]), "+f"(c[1]), "+f"(c[2]), "+f"(c[3])
                 : "r"(a[0]), "r"(a[1]), "r"(a[2]), "r"(a[3]), "r"(b0), "r"(b1));
}
__device__ __forceinline__ void hmma_f16(float c[4], const uint32_t a[4], uint32_t b0, uint32_t b1) {
    asm volatile("mma.sync.aligned.m16n8k16.row.col.f32.f16.f16.f32 "
                 "{%0,%1,%2,%3},{%4,%5,%6,%7},{%8,%9},{%0,%1,%2,%3};"
                 : "+f"(c[0]), "+f"(c[1]), "+f"(c[2]), "+f"(c[3])
                 : "r"(a[0]), "r"(a[1]), "r"(a[2]), "r"(a[3]), "r"(b0), "r"(b1));
}
#define CP16(d, s)  asm volatile("cp.async.cg.shared.global [%0], [%1], 16;" ::"r"(d), "l"(s))
#define CPCOMMIT()  asm volatile("cp.async.commit_group;" ::: "memory")
#define CPWAIT2()   asm volatile("cp.async.wait_group 2;" ::: "memory")
#define CPWAIT1()   asm volatile("cp.async.wait_group 1;" ::: "memory")
#define CPWAIT0()   asm volatile("cp.async.wait_group 0;" ::: "memory")

#define SROW 144      // 64 bf16 = 128B data + 16B pad (conflict-free ldmatrix)

// =========================== grid barrier ===================================
__device__ __forceinline__ void grid_barrier(unsigned target) {
    __threadfence();
    __syncthreads();
    if (threadIdx.x == 0) {
        unsigned total = (unsigned)NCTA * target;
        unsigned old = atomicAdd(&g_bcnt, 1u);
        if (old == total - 1u) {
            asm volatile("st.global.release.gpu.u32 [%0], %1;" ::"l"(&g_bflag), "r"(target) : "memory");
        } else {
            unsigned f;
            do {
                asm volatile("ld.global.acquire.gpu.u32 %0, [%1];" : "=r"(f) : "l"(&g_bflag) : "memory");
            } while (f < target);
        }
    }
    __syncthreads();
}

// ============================== pack weights ================================
__global__ void pack_w(const float* __restrict__ wii, const float* __restrict__ wif,
                       const float* __restrict__ wig, const float* __restrict__ wio,
                       const float* __restrict__ whi, const float* __restrict__ whf,
                       const float* __restrict__ whg, const float* __restrict__ who)
{
    __shared__ float tile[32][33];
    const float* srcs[8] = {wii, wif, wig, wio, whi, whf, whg, who};
    int z = blockIdx.z;
    const float* src = srcs[z];
    int g = z & 3;
    int k0 = blockIdx.x * 32, hc0 = blockIdx.y * 32;
    int tx = threadIdx.x, ty = threadIdx.y;   // (32, 8)
#pragma unroll
    for (int i = 0; i < 4; i++) {
        int k = k0 + ty + i * 8;
        tile[ty + i * 8][tx] = src[(size_t)k * HSZ + hc0 + tx];
    }
    __syncthreads();
#pragma unroll
    for (int i = 0; i < 4; i++) {
        int r = ty + i * 8;
        size_t np = (size_t)(hc0 + r) * 4 + g;
        float v = tile[tx][r];
        if (z < 4) {
            __nv_bfloat16 hi = __float2bfloat16(v);
            float lo = v - __bfloat162float(hi);
            g_WiT_hi[np * HSZ + k0 + tx] = hi;
            g_WiT_lo[np * HSZ + k0 + tx] = __float2bfloat16(lo);
        } else {
            __half hi = __float2half_rn(v);
            float lo = (v - __half2float(hi)) * 2048.0f;
            g_WhT_h[np * HSZ + k0 + tx] = hi;
            g_WhT_l[np * HSZ + k0 + tx] = __float2half_rn(lo);
        }
    }
}

// ======================== init state + packed bias ==========================
__global__ void init_state(const float* __restrict__ bii, const float* __restrict__ bhi,
                           const float* __restrict__ bif, const float* __restrict__ bhf,
                           const float* __restrict__ big, const float* __restrict__ bhg,
                           const float* __restrict__ bio, const float* __restrict__ bho)
{
    int i = blockIdx.x * blockDim.x + threadIdx.x;
    if (i == 0) { g_bcnt = 0u; g_bflag = 0u; }
    if (i < BATCH * HSZ) {
        __half z = __float2half_rn(0.f);
        g_h16[0][i] = z; g_h16[1][i] = z;
    }
    if (i < N4) {
        int hc = i >> 2, g = i & 3;
        const float* bi[4] = {bii, bif, big, bio};
        const float* bh[4] = {bhi, bhf, bhg, bho};
        g_bias_p[i] = bi[g][hc] + bh[g][hc];
    }
}

// =========================== x -> bf16 hi/lo split ==========================
__global__ void conv_x(const float* __restrict__ x)
{
    size_t i = (size_t)blockIdx.x * blockDim.x + threadIdx.x;   // float4 index
    float4 v = ((const float4*)x)[i];
    __nv_bfloat16 h0 = __float2bfloat16(v.x);
    __nv_bfloat16 h1 = __float2bfloat16(v.y);
    __nv_bfloat16 h2 = __float2bfloat16(v.z);
    __nv_bfloat16 h3 = __float2bfloat16(v.w);
    __nv_bfloat16 l0 = __float2bfloat16(v.x - __bfloat162float(h0));
    __nv_bfloat16 l1 = __float2bfloat16(v.y - __bfloat162float(h1));
    __nv_bfloat16 l2 = __float2bfloat16(v.z - __bfloat162float(h2));
    __nv_bfloat16 l3 = __float2bfloat16(v.w - __bfloat162float(h3));
    ((__nv_bfloat162*)g_x_hi)[i * 2]     = __halves2bfloat162(h0, h1);
    ((__nv_bfloat162*)g_x_hi)[i * 2 + 1] = __halves2bfloat162(h2, h3);
    ((__nv_bfloat162*)g_x_lo)[i * 2]     = __halves2bfloat162(l0, l1);
    ((__nv_bfloat162*)g_x_lo)[i * 2 + 1] = __halves2bfloat162(l2, l3);
}

// ========================= xproj GEMM (HMMA, bf16 3-term) ===================
#define XSTG 73728
__global__ void __launch_bounds__(256, 1) xproj_mma()
{
    extern __shared__ __align__(128) char smem[];
    const uint32_t sb = smem_u32(smem);
    const int tid = threadIdx.x;
    const int n0 = blockIdx.x * 128, m0 = blockIdx.y * 128;
    const int wid = tid >> 5, l = tid & 31;
    const int wm = wid >> 1, wn = wid & 1;    // 4 x 2 warps

    auto load_chunk = [&](int c, int st) {
        uint32_t base = sb + (uint32_t)st * XSTG;
        int ko = c * 64;
#pragma unroll
        for (int j = 0; j < 4; j++) {
            int cid = tid * 4 + j;          // 0..1023
            int row = cid >> 3, kc = cid & 7;
            uint32_t doff = row * SROW + kc * 16;
            CP16(base + doff,          g_x_hi  + (size_t)(m0 + row) * HSZ + ko + kc * 8);
            CP16(base + 18432 + doff,  g_x_lo  + (size_t)(m0 + row) * HSZ + ko + kc * 8);
            CP16(base + 36864 + doff,  g_WiT_hi + (size_t)(n0 + row) * HSZ + ko + kc * 8);
            CP16(base + 55296 + doff,  g_WiT_lo + (size_t)(n0 + row) * HSZ + ko + kc * 8);
        }
        CPCOMMIT();
    };

    float acc[2][8][4];
#pragma unroll
    for (int i = 0; i < 2; i++)
#pragma unroll
        for (int j = 0; j < 8; j++)
#pragma unroll
            for (int k = 0; k < 4; k++) acc[i][j][k] = 0.f;

    const uint32_t aoff = (wm * 32 + (l & 15)) * SROW + (l >> 4) * 16;
    const uint32_t boff = 36864u + (wn * 64 + (l & 15)) * SROW + (l >> 4) * 16;

    load_chunk(0, 0);
    load_chunk(1, 1);

    for (int c = 0; c < 16; c++) {
        if (c < 15) { CPWAIT1(); } else { CPWAIT0(); }
        __syncthreads();
        if (c + 2 < 16) load_chunk(c + 2, (c + 2) % 3);
        uint32_t base = sb + (uint32_t)(c % 3) * XSTG;
#pragma unroll
        for (int ks = 0; ks < 4; ks++) {
            uint32_t aO = base + aoff + ks * 32;
            uint32_t bO = base + boff + ks * 32;
            uint32_t ah0[4], ah1[4], al0[4], al1[4];
            ldm4(aO,              ah0);
            ldm4(aO + 16 * SROW,  ah1);
            ldm4(aO + 18432,             al0);
            ldm4(aO + 18432 + 16 * SROW, al1);
#pragma unroll
            for (int nh = 0; nh < 4; nh++) {
                uint32_t bh[4], bl[4];
                ldm4(bO + nh * 16 * SROW,         bh);
                ldm4(bO + nh * 16 * SROW + 18432, bl);
                int nb = nh * 2;
                hmma_bf16(acc[0][nb],     ah0, bh[0], bh[2]);
                hmma_bf16(acc[0][nb + 1], ah0, bh[1], bh[3]);
                hmma_bf16(acc[1][nb],     ah1, bh[0], bh[2]);
                hmma_bf16(acc[1][nb + 1], ah1, bh[1], bh[3]);
                hmma_bf16(acc[0][nb],     ah0, bl[0], bl[2]);
                hmma_bf16(acc[0][nb + 1], ah0, bl[1], bl[3]);
                hmma_bf16(acc[1][nb],     ah1, bl[0], bl[2]);
                hmma_bf16(acc[1][nb + 1], ah1, bl[1], bl[3]);
                hmma_bf16(acc[0][nb],     al0, bh[0], bh[2]);
                hmma_bf16(acc[0][nb + 1], al0, bh[1], bh[3]);
                hmma_bf16(acc[1][nb],     al1, bh[0], bh[2]);
                hmma_bf16(acc[1][nb + 1], al1, bh[1], bh[3]);
            }
        }
    }

    // epilogue: bias + store to g_xp[(t*64+b)][n'],  m = b*512 + t
#pragma unroll
    for (int mi = 0; mi < 2; mi++) {
#pragma unroll
        for (int nb = 0; nb < 8; nb++) {
            int row = m0 + wm * 32 + mi * 16 + (l >> 2);
            int col = n0 + wn * 64 + nb * 8 + 2 * (l & 3);
            float2 bv = *(const float2*)&g_bias_p[col];
            size_t r0 = ((size_t)(row & 511) * BATCH + (row >> 9)) * N4;
            *(float2*)&g_xp[r0 + col] = make_float2(acc[mi][nb][0] + bv.x,
                                                    acc[mi][nb][1] + bv.y);
            int row2 = row + 8;
            size_t r1 = ((size_t)(row2 & 511) * BATCH + (row2 >> 9)) * N4;
            *(float2*)&g_xp[r1 + col] = make_float2(acc[mi][nb][2] + bv.x,
                                                    acc[mi][nb][3] + bv.y);
        }
    }
}

// ==================== persistent recurrence (all 512 steps) =================
// 128 CTAs x 256 thr. CTA owns 32 n' rows. Wh (fp16 hi + lo*2048) resident in
// smem. Per step: stream h (single fp16) in 8 chunks of K=128 (4-stage, 3-ahead
// cp.async pipeline, ONE barrier per chunk), 2-term HMMA into separate fp32
// accumulators, combine accH + accL/2048 in epilogue, fused cell update.
#define WROW2   2064                        // 1024 fp16 = 2048B + 16B pad
#define WLO_OFF (32 * WROW2)                // 66048
#define HOFF2   (2 * 32 * WROW2)            // 132096
#define HROW2   272                         // 128 fp16 = 256B + 16B pad
#define HSTG2   (64 * HROW2)                // 17408
#define DSOFF2  (HOFF2 + 4 * HSTG2)         // 201728
#define PCOFF2  (DSOFF2 + 32 * 68 * 4)      // 210432
#define PSMEM2  (PCOFF2 + 512 * 4)          // 212480

__global__ void __launch_bounds__(256, 1) lstm_persist()
{
    extern __shared__ __align__(128) char smem[];
    const uint32_t sb = smem_u32(smem);
    const int tid = threadIdx.x;
    const int cta = blockIdx.x;
    const int n0 = cta * 32;
    const int wid = tid >> 5, l = tid & 31;
    const int wm = wid & 1, wn = wid >> 1;    // 2 m-halves x 4 n-quarters

    // ---- load resident W slice (hi & scaled-lo fp16), 128 KB ----
    for (int i = tid; i < 4096; i += 256) {
        int row = i >> 7, c16 = i & 127;
        uint32_t d = sb + row * WROW2 + c16 * 16;
        CP16(d,           g_WhT_h + (size_t)(n0 + row) * HSZ + c16 * 8);
        CP16(d + WLO_OFF, g_WhT_l + (size_t)(n0 + row) * HSZ + c16 * 8);
    }
    CPCOMMIT(); CPWAIT0();

    float* c_s = (float*)(smem + PCOFF2);
    float* Ds  = (float*)(smem + DSOFF2);
    for (int i = tid; i < 512; i += 256) c_s[i] = 0.f;
    __syncthreads();

    const uint32_t aoffh = sb + (wm * 16 + (l & 15)) * WROW2 + (l >> 4) * 16;
    const uint32_t aoffl = aoffh + WLO_OFF;
    const uint32_t boffr = (wn * 16 + (l & 15)) * HROW2 + (l >> 4) * 16;

    const int b = tid & 63, q = tid >> 6;     // cell ownership: (b, hc=2q, 2q+1)
    const int hcg0 = cta * 8 + 2 * q;

    for (int t = 0; t < SEQ; t++) {
        const __half* __restrict__ hin = g_h16[t & 1];

        // prefetch xp tile (independent of h)
        const float* xprow = g_xp + ((size_t)t * BATCH + b) * N4 + n0 + q * 8;
        float4 xpA = *(const float4*)(xprow);
        float4 xpB = *(const float4*)(xprow + 4);

        auto load_h = [&](int c, int st) {
            uint32_t base = sb + HOFF2 + (uint32_t)st * HSTG2;
            int ko = c * 128;
#pragma unroll
            for (int j = 0; j < 4; j++) {
                int cid = tid * 4 + j;        // 0..1023
                int row = cid >> 4, kc = cid & 15;
                CP16(base + row * HROW2 + kc * 16, hin + (size_t)row * HSZ + ko + kc * 8);
            }
            CPCOMMIT();
        };

        float accH[2][4], accL[2][4];
#pragma unroll
        for (int i = 0; i < 2; i++)
#pragma unroll
            for (int k = 0; k < 4; k++) { accH[i][k] = 0.f; accL[i][k] = 0.f; }

        load_h(0, 0);
        load_h(1, 1);
        load_h(2, 2);

#pragma unroll 1
        for (int c = 0; c < 8; c++) {
            if (c <= 5) { CPWAIT2(); } else if (c == 6) { CPWAIT1(); } else { CPWAIT0(); }
            __syncthreads();                      // data ready; prev chunk fully consumed
            if (c + 3 < 8) load_h(c + 3, (c + 3) & 3);
            uint32_t wbase = c * 256;             // byte offset into W row (K-major)
            uint32_t hb = sb + HOFF2 + (uint32_t)(c & 3) * HSTG2 + boffr;
#pragma unroll
            for (int ks = 0; ks < 8; ks++) {
                uint32_t ah[4], al[4], bh[4];
                ldm4(aoffh + wbase + ks * 32, ah);
                ldm4(aoffl + wbase + ks * 32, al);
                ldm4(hb + ks * 32, bh);
                hmma_f16(accH[0], ah, bh[0], bh[2]);
                hmma_f16(accH[1], ah, bh[1], bh[3]);
                hmma_f16(accL[0], al, bh[0], bh[2]);
                hmma_f16(accL[1], al, bh[1], bh[3]);
            }
        }

        // D [32 n'][64 b] -> smem (combine lo term)
        {
            int r = wm * 16 + (l >> 2);
#pragma unroll
            for (int nb = 0; nb < 2; nb++) {
                int col = wn * 16 + nb * 8 + 2 * (l & 3);
                const float s = 1.0f / 2048.0f;
                Ds[r * 68 + col]           = accH[nb][0] + accL[nb][0] * s;
                Ds[r * 68 + col + 1]       = accH[nb][1] + accL[nb][1] * s;
                Ds[(r + 8) * 68 + col]     = accH[nb][2] + accL[nb][2] * s;
                Ds[(r + 8) * 68 + col + 1] = accH[nb][3] + accL[nb][3] * s;
            }
        }
        __syncthreads();

        // fused cell update: this thread owns (b, hc=2q) and (b, hc=2q+1)
        float hv[2];
#pragma unroll
        for (int j = 0; j < 2; j++) {
            int hcl = 2 * q + j;
            float iv = Ds[(hcl * 4 + 0) * 68 + b];
            float fv = Ds[(hcl * 4 + 1) * 68 + b];
            float gv = Ds[(hcl * 4 + 2) * 68 + b];
            float ov = Ds[(hcl * 4 + 3) * 68 + b];
            float xi = j ? xpB.x : xpA.x;
            float xf = j ? xpB.y : xpA.y;
            float xg = j ? xpB.z : xpA.z;
            float xo = j ? xpB.w : xpA.w;
            float ig = 1.0f / (1.0f + expf(-(iv + xi)));
            float fg = 1.0f / (1.0f + expf(-(fv + xf)));
            float gg = tanhf(gv + xg);
            float og = 1.0f / (1.0f + expf(-(ov + xo)));
            int ci = b * 8 + hcl;
            float cnew = c_s[ci] * fg + ig * gg;
            c_s[ci] = cnew;
            hv[j] = og * tanhf(cnew);
        }
        {
            int idx = b * HSZ + hcg0;
            *(__half2*)(g_h16[(t + 1) & 1] + idx) =
                __halves2half2(__float2half_rn(hv[0]), __float2half_rn(hv[1]));
            if (t == SEQ - 1) {
                *(float2*)(g_hf + idx) = make_float2(hv[0], hv[1]);
                *(float2*)(g_c  + idx) = make_float2(c_s[b * 8 + 2 * q], c_s[b * 8 + 2 * q + 1]);
            }
        }

        if (t < SEQ - 1) grid_barrier((unsigned)(t + 1));
    }
}

// ============================== output ======================================
__global__ void copy_out_kernel(float* __restrict__ out, int n)
{
    int i = blockIdx.x * blockDim.x + threadIdx.x;
    if (i >= n) return;
    if (i < BATCH * HSZ)          out[i] = g_hf[i];
    else if (i < 2 * BATCH * HSZ) out[i] = g_c[i - BATCH * HSZ];
    else                          out[i] = 0.0f;
}

// ============================== launcher ====================================
extern "C" void kernel_launch(void* const* d_in, const int* in_sizes, int n_in,
                              void* d_out, int out_size)
{
    const float* x   = (const float*)d_in[0];
    const float* wii = (const float*)d_in[1];
    const float* bii = (const float*)d_in[2];
    const float* whi = (const float*)d_in[3];
    const float* bhi = (const float*)d_in[4];
    const float* wif = (const float*)d_in[5];
    const float* bif = (const float*)d_in[6];
    const float* whf = (const float*)d_in[7];
    const float* bhf = (const float*)d_in[8];
    const float* wig = (const float*)d_in[9];
    const float* big = (const float*)d_in[10];
    const float* whg = (const float*)d_in[11];
    const float* bhg = (const float*)d_in[12];
    const float* wio = (const float*)d_in[13];
    const float* bio = (const float*)d_in[14];
    const float* who = (const float*)d_in[15];
    const float* bho = (const float*)d_in[16];
    (void)in_sizes; (void)n_in;

    static int configured = 0;
    if (!configured) {
        cudaFuncSetAttribute(xproj_mma,    cudaFuncAttributeMaxDynamicSharedMemorySize, 3 * XSTG);
        cudaFuncSetAttribute(lstm_persist, cudaFuncAttributeMaxDynamicSharedMemorySize, PSMEM2);
        configured = 1;
    }

    pack_w<<<dim3(32, 32, 8), dim3(32, 8)>>>(wii, wif, wig, wio, whi, whf, whg, who);
    init_state<<<(BATCH * HSZ + 255) / 256, 256>>>(bii, bhi, bif, bhf, big, bhg, bio, bho);
    conv_x<<<(MTOT * HSZ / 4 + 255) / 256, 256>>>(x);

    xproj_mma<<<dim3(32, 256), 256, 3 * XSTG>>>();

    lstm_persist<<<NCTA, 256, PSMEM2>>>();

    copy_out_kernel<<<(out_size + 255) / 256, 256>>>((float*)d_out, out_size);
}

// round 6
// speedup vs baseline: 4.9851x; 1.0029x over previous
#include <cuda_runtime.h>
#include <cuda_bf16.h>
#include <cuda_fp16.h>
#include <math.h>
#include <stdint.h>

#define BATCH 64
#define SEQ   512
#define HSZ   1024
#define N4    4096
#define MTOT  (BATCH * SEQ)   // 32768
#define NCTA  128

// ============================ device scratch ================================
__device__ __align__(128) __nv_bfloat16 g_WiT_hi[(size_t)N4 * HSZ]; // [n'][k]
__device__ __align__(128) __nv_bfloat16 g_WiT_lo[(size_t)N4 * HSZ];
__device__ __align__(128) __half g_WhT_h[(size_t)N4 * HSZ];         // fp16 hi
__device__ __align__(128) __half g_WhT_l[(size_t)N4 * HSZ];         // fp16 (lo*2048)
__device__ __align__(128) __nv_bfloat16 g_x_hi[(size_t)MTOT * HSZ]; // [b*512+t][k]
__device__ __align__(128) __nv_bfloat16 g_x_lo[(size_t)MTOT * HSZ];
__device__ __align__(128) float g_bias_p[N4];
__device__ __align__(128) float g_xp[(size_t)MTOT * N4];            // [t*64+b][n']
__device__ __align__(128) __half g_h16[2][BATCH * HSZ];
__device__ __align__(128) float g_hf[BATCH * HSZ];
__device__ __align__(128) float g_c[BATCH * HSZ];
__device__ unsigned g_bcnt;
__device__ unsigned g_bflag;

// ============================ PTX helpers ===================================
__device__ __forceinline__ uint32_t smem_u32(const void* p) {
    uint32_t a;
    asm("{ .reg .u64 t; cvta.to.shared.u64 t, %1; cvt.u32.u64 %0, t; }" : "=r"(a) : "l"(p));
    return a;
}
__device__ __forceinline__ void ldm4(uint32_t addr, uint32_t r[4]) {
    asm volatile("ldmatrix.sync.aligned.m8n8.x4.shared.b16 {%0,%1,%2,%3}, [%4];"
                 : "=r"(r[0]), "=r"(r[1]), "=r"(r[2]), "=r"(r[3]) : "r"(addr));
}
__device__ __forceinline__ void hmma_bf16(float c[4], const uint32_t a[4], uint32_t b0, uint32_t b1) {
    asm volatile("mma.sync.aligned.m16n8k16.row.col.f32.bf16.bf16.f32 "
                 "{%0,%1,%2,%3},{%4,%5,%6,%7},{%8,%9},{%0,%1,%2,%3};"
                 : "+f"(c[0]), "+f"(c[1]), "+f"(c[2]), "+f"(c[3])
                 : "r"(a[0]), "r"(a[1]), "r"(a[2]), "r"(a[3]), "r"(b0), "r"(b1));
}
__device__ __forceinline__ void hmma_f16(float c[4], const uint32_t a[4], uint32_t b0, uint32_t b1) {
    asm volatile("mma.sync.aligned.m16n8k16.row.col.f32.f16.f16.f32 "
                 "{%0,%1,%2,%3},{%4,%5,%6,%7},{%8,%9},{%0,%1,%2,%3};"
                 : "+f"(c[0]), "+f"(c[1]), "+f"(c[2]), "+f"(c[3])
                 : "r"(a[0]), "r"(a[1]), "r"(a[2]), "r"(a[3]), "r"(b0), "r"(b1));
}
#define CP16(d, s)  asm volatile("cp.async.cg.shared.global [%0], [%1], 16;" ::"r"(d), "l"(s))
#define CPCOMMIT()  asm volatile("cp.async.commit_group;" ::: "memory")
#define CPWAIT2()   asm volatile("cp.async.wait_group 2;" ::: "memory")
#define CPWAIT1()   asm volatile("cp.async.wait_group 1;" ::: "memory")
#define CPWAIT0()   asm volatile("cp.async.wait_group 0;" ::: "memory")

#define SROW 144      // 64 bf16 = 128B data + 16B pad (conflict-free ldmatrix)

// =========================== grid barrier ===================================
__device__ __forceinline__ void grid_barrier(unsigned target) {
    __threadfence();
    __syncthreads();
    if (threadIdx.x == 0) {
        unsigned total = (unsigned)NCTA * target;
        unsigned old = atomicAdd(&g_bcnt, 1u);
        if (old == total - 1u) {
            asm volatile("st.global.release.gpu.u32 [%0], %1;" ::"l"(&g_bflag), "r"(target) : "memory");
        } else {
            unsigned f;
            do {
                asm volatile("ld.global.acquire.gpu.u32 %0, [%1];" : "=r"(f) : "l"(&g_bflag) : "memory");
            } while (f < target);
        }
    }
    __syncthreads();
}

// ============================== pack weights ================================
__global__ void pack_w(const float* __restrict__ wii, const float* __restrict__ wif,
                       const float* __restrict__ wig, const float* __restrict__ wio,
                       const float* __restrict__ whi, const float* __restrict__ whf,
                       const float* __restrict__ whg, const float* __restrict__ who)
{
    __shared__ float tile[32][33];
    const float* srcs[8] = {wii, wif, wig, wio, whi, whf, whg, who};
    int z = blockIdx.z;
    const float* src = srcs[z];
    int g = z & 3;
    int k0 = blockIdx.x * 32, hc0 = blockIdx.y * 32;
    int tx = threadIdx.x, ty = threadIdx.y;   // (32, 8)
#pragma unroll
    for (int i = 0; i < 4; i++) {
        int k = k0 + ty + i * 8;
        tile[ty + i * 8][tx] = src[(size_t)k * HSZ + hc0 + tx];
    }
    __syncthreads();
#pragma unroll
    for (int i = 0; i < 4; i++) {
        int r = ty + i * 8;
        size_t np = (size_t)(hc0 + r) * 4 + g;
        float v = tile[tx][r];
        if (z < 4) {
            __nv_bfloat16 hi = __float2bfloat16(v);
            float lo = v - __bfloat162float(hi);
            g_WiT_hi[np * HSZ + k0 + tx] = hi;
            g_WiT_lo[np * HSZ + k0 + tx] = __float2bfloat16(lo);
        } else {
            __half hi = __float2half_rn(v);
            float lo = (v - __half2float(hi)) * 2048.0f;
            g_WhT_h[np * HSZ + k0 + tx] = hi;
            g_WhT_l[np * HSZ + k0 + tx] = __float2half_rn(lo);
        }
    }
}

// ======================== init state + packed bias ==========================
__global__ void init_state(const float* __restrict__ bii, const float* __restrict__ bhi,
                           const float* __restrict__ bif, const float* __restrict__ bhf,
                           const float* __restrict__ big, const float* __restrict__ bhg,
                           const float* __restrict__ bio, const float* __restrict__ bho)
{
    int i = blockIdx.x * blockDim.x + threadIdx.x;
    if (i == 0) { g_bcnt = 0u; g_bflag = 0u; }
    if (i < BATCH * HSZ) {
        __half z = __float2half_rn(0.f);
        g_h16[0][i] = z; g_h16[1][i] = z;
    }
    if (i < N4) {
        int hc = i >> 2, g = i & 3;
        const float* bi[4] = {bii, bif, big, bio};
        const float* bh[4] = {bhi, bhf, bhg, bho};
        g_bias_p[i] = bi[g][hc] + bh[g][hc];
    }
}

// =========================== x -> bf16 hi/lo split ==========================
__global__ void conv_x(const float* __restrict__ x)
{
    size_t i = (size_t)blockIdx.x * blockDim.x + threadIdx.x;   // float4 index
    float4 v = ((const float4*)x)[i];
    __nv_bfloat16 h0 = __float2bfloat16(v.x);
    __nv_bfloat16 h1 = __float2bfloat16(v.y);
    __nv_bfloat16 h2 = __float2bfloat16(v.z);
    __nv_bfloat16 h3 = __float2bfloat16(v.w);
    __nv_bfloat16 l0 = __float2bfloat16(v.x - __bfloat162float(h0));
    __nv_bfloat16 l1 = __float2bfloat16(v.y - __bfloat162float(h1));
    __nv_bfloat16 l2 = __float2bfloat16(v.z - __bfloat162float(h2));
    __nv_bfloat16 l3 = __float2bfloat16(v.w - __bfloat162float(h3));
    ((__nv_bfloat162*)g_x_hi)[i * 2]     = __halves2bfloat162(h0, h1);
    ((__nv_bfloat162*)g_x_hi)[i * 2 + 1] = __halves2bfloat162(h2, h3);
    ((__nv_bfloat162*)g_x_lo)[i * 2]     = __halves2bfloat162(l0, l1);
    ((__nv_bfloat162*)g_x_lo)[i * 2 + 1] = __halves2bfloat162(l2, l3);
}

// ========================= xproj GEMM (HMMA, bf16 3-term) ===================
#define XSTG 73728
__global__ void __launch_bounds__(256, 1) xproj_mma()
{
    extern __shared__ __align__(128) char smem[];
    const uint32_t sb = smem_u32(smem);
    const int tid = threadIdx.x;
    const int n0 = blockIdx.x * 128, m0 = blockIdx.y * 128;
    const int wid = tid >> 5, l = tid & 31;
    const int wm = wid >> 1, wn = wid & 1;    // 4 x 2 warps

    auto load_chunk = [&](int c, int st) {
        uint32_t base = sb + (uint32_t)st * XSTG;
        int ko = c * 64;
#pragma unroll
        for (int j = 0; j < 4; j++) {
            int cid = tid * 4 + j;          // 0..1023
            int row = cid >> 3, kc = cid & 7;
            uint32_t doff = row * SROW + kc * 16;
            CP16(base + doff,          g_x_hi  + (size_t)(m0 + row) * HSZ + ko + kc * 8);
            CP16(base + 18432 + doff,  g_x_lo  + (size_t)(m0 + row) * HSZ + ko + kc * 8);
            CP16(base + 36864 + doff,  g_WiT_hi + (size_t)(n0 + row) * HSZ + ko + kc * 8);
            CP16(base + 55296 + doff,  g_WiT_lo + (size_t)(n0 + row) * HSZ + ko + kc * 8);
        }
        CPCOMMIT();
    };

    float acc[2][8][4];
#pragma unroll
    for (int i = 0; i < 2; i++)
#pragma unroll
        for (int j = 0; j < 8; j++)
#pragma unroll
            for (int k = 0; k < 4; k++) acc[i][j][k] = 0.f;

    const uint32_t aoff = (wm * 32 + (l & 15)) * SROW + (l >> 4) * 16;
    const uint32_t boff = 36864u + (wn * 64 + (l & 15)) * SROW + (l >> 4) * 16;

    load_chunk(0, 0);
    load_chunk(1, 1);

    for (int c = 0; c < 16; c++) {
        if (c < 15) { CPWAIT1(); } else { CPWAIT0(); }
        __syncthreads();
        if (c + 2 < 16) load_chunk(c + 2, (c + 2) % 3);
        uint32_t base = sb + (uint32_t)(c % 3) * XSTG;
#pragma unroll
        for (int ks = 0; ks < 4; ks++) {
            uint32_t aO = base + aoff + ks * 32;
            uint32_t bO = base + boff + ks * 32;
            uint32_t ah0[4], ah1[4], al0[4], al1[4];
            ldm4(aO,              ah0);
            ldm4(aO + 16 * SROW,  ah1);
            ldm4(aO + 18432,             al0);
            ldm4(aO + 18432 + 16 * SROW, al1);
#pragma unroll
            for (int nh = 0; nh < 4; nh++) {
                uint32_t bh[4], bl[4];
                ldm4(bO + nh * 16 * SROW,         bh);
                ldm4(bO + nh * 16 * SROW + 18432, bl);
                int nb = nh * 2;
                hmma_bf16(acc[0][nb],     ah0, bh[0], bh[2]);
                hmma_bf16(acc[0][nb + 1], ah0, bh[1], bh[3]);
                hmma_bf16(acc[1][nb],     ah1, bh[0], bh[2]);
                hmma_bf16(acc[1][nb + 1], ah1, bh[1], bh[3]);
                hmma_bf16(acc[0][nb],     ah0, bl[0], bl[2]);
                hmma_bf16(acc[0][nb + 1], ah0, bl[1], bl[3]);
                hmma_bf16(acc[1][nb],     ah1, bl[0], bl[2]);
                hmma_bf16(acc[1][nb + 1], ah1, bl[1], bl[3]);
                hmma_bf16(acc[0][nb],     al0, bh[0], bh[2]);
                hmma_bf16(acc[0][nb + 1], al0, bh[1], bh[3]);
                hmma_bf16(acc[1][nb],     al1, bh[0], bh[2]);
                hmma_bf16(acc[1][nb + 1], al1, bh[1], bh[3]);
            }
        }
    }

    // epilogue: bias + store to g_xp[(t*64+b)][n'],  m = b*512 + t
#pragma unroll
    for (int mi = 0; mi < 2; mi++) {
#pragma unroll
        for (int nb = 0; nb < 8; nb++) {
            int row = m0 + wm * 32 + mi * 16 + (l >> 2);
            int col = n0 + wn * 64 + nb * 8 + 2 * (l & 3);
            float2 bv = *(const float2*)&g_bias_p[col];
            size_t r0 = ((size_t)(row & 511) * BATCH + (row >> 9)) * N4;
            *(float2*)&g_xp[r0 + col] = make_float2(acc[mi][nb][0] + bv.x,
                                                    acc[mi][nb][1] + bv.y);
            int row2 = row + 8;
            size_t r1 = ((size_t)(row2 & 511) * BATCH + (row2 >> 9)) * N4;
            *(float2*)&g_xp[r1 + col] = make_float2(acc[mi][nb][2] + bv.x,
                                                    acc[mi][nb][3] + bv.y);
        }
    }
}

// ==================== persistent recurrence (all 512 steps) =================
// 128 CTAs x 256 thr. CTA owns 32 n' rows. Wh (fp16 hi + lo*2048) resident in
// smem. Per step: stream h (single fp16) in 8 chunks of K=128 (4-stage, 3-ahead
// cp.async pipeline, ONE barrier per chunk), 2-term HMMA into separate fp32
// accumulators, combine accH + accL/2048 in epilogue, fused cell update.
#define WROW2   2064                        // 1024 fp16 = 2048B + 16B pad
#define WLO_OFF (32 * WROW2)                // 66048
#define HOFF2   (2 * 32 * WROW2)            // 132096
#define HROW2   272                         // 128 fp16 = 256B + 16B pad
#define HSTG2   (64 * HROW2)                // 17408
#define DSOFF2  (HOFF2 + 4 * HSTG2)         // 201728
#define PCOFF2  (DSOFF2 + 32 * 68 * 4)      // 210432
#define PSMEM2  (PCOFF2 + 512 * 4)          // 212480

__global__ void __launch_bounds__(256, 1) lstm_persist()
{
    extern __shared__ __align__(128) char smem[];
    const uint32_t sb = smem_u32(smem);
    const int tid = threadIdx.x;
    const int cta = blockIdx.x;
    const int n0 = cta * 32;
    const int wid = tid >> 5, l = tid & 31;
    const int wm = wid & 1, wn = wid >> 1;    // 2 m-halves x 4 n-quarters

    // ---- load resident W slice (hi & scaled-lo fp16), 128 KB ----
    for (int i = tid; i < 4096; i += 256) {
        int row = i >> 7, c16 = i & 127;
        uint32_t d = sb + row * WROW2 + c16 * 16;
        CP16(d,           g_WhT_h + (size_t)(n0 + row) * HSZ + c16 * 8);
        CP16(d + WLO_OFF, g_WhT_l + (size_t)(n0 + row) * HSZ + c16 * 8);
    }
    CPCOMMIT(); CPWAIT0();

    float* c_s = (float*)(smem + PCOFF2);
    float* Ds  = (float*)(smem + DSOFF2);
    for (int i = tid; i < 512; i += 256) c_s[i] = 0.f;
    __syncthreads();

    const uint32_t aoffh = sb + (wm * 16 + (l & 15)) * WROW2 + (l >> 4) * 16;
    const uint32_t aoffl = aoffh + WLO_OFF;
    const uint32_t boffr = (wn * 16 + (l & 15)) * HROW2 + (l >> 4) * 16;

    const int b = tid & 63, q = tid >> 6;     // cell ownership: (b, hc=2q, 2q+1)
    const int hcg0 = cta * 8 + 2 * q;

    for (int t = 0; t < SEQ; t++) {
        const __half* __restrict__ hin = g_h16[t & 1];

        // prefetch xp tile (independent of h)
        const float* xprow = g_xp + ((size_t)t * BATCH + b) * N4 + n0 + q * 8;
        float4 xpA = *(const float4*)(xprow);
        float4 xpB = *(const float4*)(xprow + 4);

        auto load_h = [&](int c, int st) {
            uint32_t base = sb + HOFF2 + (uint32_t)st * HSTG2;
            int ko = c * 128;
#pragma unroll
            for (int j = 0; j < 4; j++) {
                int cid = tid * 4 + j;        // 0..1023
                int row = cid >> 4, kc = cid & 15;
                CP16(base + row * HROW2 + kc * 16, hin + (size_t)row * HSZ + ko + kc * 8);
            }
            CPCOMMIT();
        };

        float accH[2][4], accL[2][4];
#pragma unroll
        for (int i = 0; i < 2; i++)
#pragma unroll
            for (int k = 0; k < 4; k++) { accH[i][k] = 0.f; accL[i][k] = 0.f; }

        load_h(0, 0);
        load_h(1, 1);
        load_h(2, 2);

#pragma unroll 1
        for (int c = 0; c < 8; c++) {
            if (c <= 5) { CPWAIT2(); } else if (c == 6) { CPWAIT1(); } else { CPWAIT0(); }
            __syncthreads();                      // data ready; prev chunk fully consumed
            if (c + 3 < 8) load_h(c + 3, (c + 3) & 3);
            uint32_t wbase = c * 256;             // byte offset into W row (K-major)
            uint32_t hb = sb + HOFF2 + (uint32_t)(c & 3) * HSTG2 + boffr;
#pragma unroll
            for (int ks = 0; ks < 8; ks++) {
                uint32_t ah[4], al[4], bh[4];
                ldm4(aoffh + wbase + ks * 32, ah);
                ldm4(aoffl + wbase + ks * 32, al);
                ldm4(hb + ks * 32, bh);
                hmma_f16(accH[0], ah, bh[0], bh[2]);
                hmma_f16(accH[1], ah, bh[1], bh[3]);
                hmma_f16(accL[0], al, bh[0], bh[2]);
                hmma_f16(accL[1], al, bh[1], bh[3]);
            }
        }

        // D [32 n'][64 b] -> smem (combine lo term)
        {
            int r = wm * 16 + (l >> 2);
#pragma unroll
            for (int nb = 0; nb < 2; nb++) {
                int col = wn * 16 + nb * 8 + 2 * (l & 3);
                const float s = 1.0f / 2048.0f;
                Ds[r * 68 + col]           = accH[nb][0] + accL[nb][0] * s;
                Ds[r * 68 + col + 1]       = accH[nb][1] + accL[nb][1] * s;
                Ds[(r + 8) * 68 + col]     = accH[nb][2] + accL[nb][2] * s;
                Ds[(r + 8) * 68 + col + 1] = accH[nb][3] + accL[nb][3] * s;
            }
        }
        __syncthreads();

        // fused cell update: this thread owns (b, hc=2q) and (b, hc=2q+1)
        float hv[2];
#pragma unroll
        for (int j = 0; j < 2; j++) {
            int hcl = 2 * q + j;
            float iv = Ds[(hcl * 4 + 0) * 68 + b];
            float fv = Ds[(hcl * 4 + 1) * 68 + b];
            float gv = Ds[(hcl * 4 + 2) * 68 + b];
            float ov = Ds[(hcl * 4 + 3) * 68 + b];
            float xi = j ? xpB.x : xpA.x;
            float xf = j ? xpB.y : xpA.y;
            float xg = j ? xpB.z : xpA.z;
            float xo = j ? xpB.w : xpA.w;
            float ig = 1.0f / (1.0f + expf(-(iv + xi)));
            float fg = 1.0f / (1.0f + expf(-(fv + xf)));
            float gg = tanhf(gv + xg);
            float og = 1.0f / (1.0f + expf(-(ov + xo)));
            int ci = b * 8 + hcl;
            float cnew = c_s[ci] * fg + ig * gg;
            c_s[ci] = cnew;
            hv[j] = og * tanhf(cnew);
        }
        {
            int idx = b * HSZ + hcg0;
            *(__half2*)(g_h16[(t + 1) & 1] + idx) =
                __halves2half2(__float2half_rn(hv[0]), __float2half_rn(hv[1]));
            if (t == SEQ - 1) {
                *(float2*)(g_hf + idx) = make_float2(hv[0], hv[1]);
                *(float2*)(g_c  + idx) = make_float2(c_s[b * 8 + 2 * q], c_s[b * 8 + 2 * q + 1]);
            }
        }

        if (t < SEQ - 1) grid_barrier((unsigned)(t + 1));
    }
}

// ============================== output ======================================
__global__ void copy_out_kernel(float* __restrict__ out, int n)
{
    int i = blockIdx.x * blockDim.x + threadIdx.x;
    if (i >= n) return;
    if (i < BATCH * HSZ)          out[i] = g_hf[i];
    else if (i < 2 * BATCH * HSZ) out[i] = g_c[i - BATCH * HSZ];
    else                          out[i] = 0.0f;
}

// ============================== launcher ====================================
extern "C" void kernel_launch(void* const* d_in, const int* in_sizes, int n_in,
                              void* d_out, int out_size)
{
    const float* x   = (const float*)d_in[0];
    const float* wii = (const float*)d_in[1];
    const float* bii = (const float*)d_in[2];
    const float* whi = (const float*)d_in[3];
    const float* bhi = (const float*)d_in[4];
    const float* wif = (const float*)d_in[5];
    const float* bif = (const float*)d_in[6];
    const float* whf = (const float*)d_in[7];
    const float* bhf = (const float*)d_in[8];
    const float* wig = (const float*)d_in[9];
    const float* big = (const float*)d_in[10];
    const float* whg = (const float*)d_in[11];
    const float* bhg = (const float*)d_in[12];
    const float* wio = (const float*)d_in[13];
    const float* bio = (const float*)d_in[14];
    const float* who = (const float*)d_in[15];
    const float* bho = (const float*)d_in[16];
    (void)in_sizes; (void)n_in;

    static int configured = 0;
    if (!configured) {
        cudaFuncSetAttribute(xproj_mma,    cudaFuncAttributeMaxDynamicSharedMemorySize, 3 * XSTG);
        cudaFuncSetAttribute(lstm_persist, cudaFuncAttributeMaxDynamicSharedMemorySize, PSMEM2);
        configured = 1;
    }

    pack_w<<<dim3(32, 32, 8), dim3(32, 8)>>>(wii, wif, wig, wio, whi, whf, whg, who);
    init_state<<<(BATCH * HSZ + 255) / 256, 256>>>(bii, bhi, bif, bhf, big, bhg, bio, bho);
    conv_x<<<(MTOT * HSZ / 4 + 255) / 256, 256>>>(x);

    xproj_mma<<<dim3(32, 256), 256, 3 * XSTG>>>();

    lstm_persist<<<NCTA, 256, PSMEM2>>>();

    copy_out_kernel<<<(out_size + 255) / 256, 256>>>((float*)d_out, out_size);
}